// round 4
// baseline (speedup 1.0000x reference)
#include <cuda_runtime.h>
#include <math.h>
#include <stdint.h>

// Problem dims
#define BATCH 128
#define TT    512
#define DIM   512
#define HDIM  512
#define ODIM  256
#define NCOL  1536   // 3*HDIM

// Recurrence partition: 4 row-groups x 32 rows; 32 CTAs per group (column slices)
#define NG  4
#define RG  32
#define NC  32
#define NCTA (NG*NC)
#define NTH 256

#define RZ_COLS 32   // pre-activation columns in [0,1024) per CTA
#define XS_COLS 16   // hdim slice of [1024,1536) per CTA
#define XO_COLS 8    // output columns of Wxo per CTA

// Shared memory layout (floats). AST=34: even (8B-aligned u64 loads) and only
// 2-way bank conflict on transposed staging stores.
#define AST      34
#define SM_ACT   0
#define SM_RS    (768*AST)                 // 26112
#define SM_XS    (SM_RS + 512*AST)         // 43520
#define SM_RED   (SM_XS + RG*XS_COLS)      // 44032
#define SM_TOTAL (SM_RED + 3584)           // 47616 floats = 190464 bytes

typedef unsigned long long u64;

__device__ __forceinline__ u64 pack2(float lo, float hi) {
    u64 r; asm("mov.b64 %0,{%1,%2};" : "=l"(r) : "f"(lo), "f"(hi)); return r;
}
__device__ __forceinline__ void unpack2(u64 v, float& lo, float& hi) {
    asm("mov.b64 {%0,%1},%2;" : "=f"(lo), "=f"(hi) : "l"(v));
}
__device__ __forceinline__ void fma2(u64& d, u64 a, u64 b) {
    asm("fma.rn.f32x2 %0,%1,%2,%0;" : "+l"(d) : "l"(a), "l"(b));
}
__device__ __forceinline__ u64 dup2(float w) { return pack2(w, w); }

// ---------------- device scratch ----------------
__device__ float g_hV[(size_t)TT * BATCH * NCOL];  // precomputed hV[t][b][j]
__device__ float g_s [BATCH * HDIM];
__device__ float g_x [BATCH * ODIM];
__device__ float g_rs[BATCH * HDIM];
__device__ float g_z [BATCH * HDIM];
__device__ unsigned g_bar[NG];

__device__ __forceinline__ float sigf(float x) { return 1.0f / (1.0f + expf(-x)); }

// ---------------- init ----------------
__global__ void init_kernel(const float* __restrict__ H) {
    int i = blockIdx.x * blockDim.x + threadIdx.x;
    if (i < NG) g_bar[i] = 0u;
    if (i < BATCH * HDIM) g_s[i] = 0.0f;
    if (i < BATCH * ODIM) {
        int b = i >> 8, o = i & 255;
        const float* h = H + ((size_t)b * TT + (TT - 1)) * DIM;
        g_x[i] = h[o] + h[o + ODIM];
    }
}

// ---------------- hV GEMM (f32x2): hV[t][b][j] = sum_d H[b][511-t][d]*Vcat[d][j] ----------------
#define GT_N 128
#define GT_K 8
__global__ void __launch_bounds__(256, 2)
hv_gemm(const float* __restrict__ H,
        const float* __restrict__ Vr,
        const float* __restrict__ Vz,
        const float* __restrict__ Vs) {
    int t  = blockIdx.y;
    int jt = blockIdx.x;
    const float* V = (jt < 4) ? Vr : ((jt < 8) ? Vz : Vs);
    int col0 = (jt & 3) * GT_N;
    const float* A = H + (size_t)(TT - 1 - t) * DIM;

    __shared__ float Ash[GT_K][BATCH + 4];   // row stride 132 floats (16B-mult rows)
    __shared__ float Bsh[GT_K][GT_N];

    int tx = threadIdx.x & 15, ty = threadIdx.x >> 4;
    u64 acc[4][8];
    #pragma unroll
    for (int i = 0; i < 4; i++)
        #pragma unroll
        for (int j = 0; j < 8; j++) acc[i][j] = 0ull;

    for (int k0 = 0; k0 < DIM; k0 += GT_K) {
        for (int i = threadIdx.x; i < BATCH * GT_K; i += 256) {
            int bb = i >> 3, dd = i & 7;
            Ash[dd][bb] = A[(size_t)bb * (TT * DIM) + k0 + dd];
        }
        for (int i = threadIdx.x; i < GT_K * GT_N; i += 256) {
            int dd = i >> 7, jj = i & 127;
            Bsh[dd][jj] = V[(size_t)(k0 + dd) * HDIM + col0 + jj];
        }
        __syncthreads();
        #pragma unroll
        for (int kk = 0; kk < GT_K; kk++) {
            const u64* ap0 = (const u64*)&Ash[kk][ty * 4];
            const u64* ap1 = (const u64*)&Ash[kk][64 + ty * 4];
            u64 av[4] = { ap0[0], ap0[1], ap1[0], ap1[1] };
            u64 bv[8];
            #pragma unroll
            for (int j = 0; j < 8; j++) {
                float b = (j < 4) ? Bsh[kk][tx * 4 + j] : Bsh[kk][64 + tx * 4 + (j - 4)];
                bv[j] = dup2(b);
            }
            #pragma unroll
            for (int i = 0; i < 4; i++)
                #pragma unroll
                for (int j = 0; j < 8; j++)
                    fma2(acc[i][j], av[i], bv[j]);
        }
        __syncthreads();
    }
    float* outp = g_hV + (size_t)t * BATCH * NCOL + jt * GT_N;
    int rowb[4] = { ty * 4, ty * 4 + 2, 64 + ty * 4, 64 + ty * 4 + 2 };
    #pragma unroll
    for (int i = 0; i < 4; i++)
        #pragma unroll
        for (int j = 0; j < 8; j++) {
            float lo, hi; unpack2(acc[i][j], lo, hi);
            int jc = (j < 4) ? (tx * 4 + j) : (64 + tx * 4 + (j - 4));
            outp[(size_t)rowb[i] * NCOL + jc]       = lo;
            outp[(size_t)(rowb[i] + 1) * NCOL + jc] = hi;
        }
}

// ---------------- group barrier ----------------
__device__ __forceinline__ void group_barrier(int g, unsigned* target) {
    __syncthreads();
    if (threadIdx.x == 0) {
        *target += NC;
        __threadfence();
        atomicAdd(&g_bar[g], 1u);
        volatile unsigned* p = &g_bar[g];
        unsigned tg = *target;
        while (*p < tg) { }
        __threadfence();
    }
    __syncthreads();
}

// ---------------- persistent recurrence kernel ----------------
__global__ void __launch_bounds__(NTH, 1)
recur_kernel(const float* __restrict__ W,   // [256][1536]
             const float* __restrict__ Bb,  // [1536]
             const float* __restrict__ U,   // [512][1536]
             const float* __restrict__ Wx,  // [512][768], Wxo = cols [0,256)
             const float* __restrict__ bx,  // [256]
             float* __restrict__ out)       // [128][512][256]
{
    extern __shared__ float sm[];
    float* actT  = sm + SM_ACT;   // [768][34] transposed: rows 0..255 x, 256..767 s
    float* rsT   = sm + SM_RS;    // [512][34] transposed r*s
    float* xs_sh = sm + SM_XS;    // [32][16]
    float* red   = sm + SM_RED;   // k-split reduction scratch (3584 floats)

    const int cta = blockIdx.x;
    const int g   = cta >> 5;
    const int c   = cta & 31;
    const int tid = threadIdx.x;
    const int row0 = g * RG;

    const int jrz = c * RZ_COLS;
    const int kcs = c * XS_COLS;
    const int o0  = c * XO_COLS;

    unsigned bar_target = 0;

    // Initial staging
    for (int i = tid; i < RG * ODIM; i += NTH) {
        int r = i >> 8, k = i & 255;
        actT[k * AST + r] = g_x[(row0 + r) * ODIM + k];
    }
    for (int i = tid; i < RG * HDIM; i += NTH) {
        int r = i >> 9, k = i & 511;
        actT[(256 + k) * AST + r] = g_s[(row0 + r) * HDIM + k];
    }
    __syncthreads();

    for (int t = 0; t < TT; t++) {
        const float* hvt = g_hV + (size_t)t * BATCH * NCOL;

        //==================== A1: pre for j in [0,1024) ====================
        // 32 cols x (2 row-blocks of 16) x (4-way k-split of 768)
        {
            int lane = tid & 31;
            int wrp  = tid >> 5;
            int rb = wrp & 1, kq = wrp >> 1;
            int rbase = rb * 16;
            int j = jrz + lane;
            u64 acc[8];
            #pragma unroll
            for (int p = 0; p < 8; p++) acc[p] = 0ull;

            int k0 = kq * 192, k1 = k0 + 192;
            // x part (W rows k<256)
            int ke = (k1 < 256) ? k1 : 256;
            const float* wp = W + (size_t)k0 * NCOL + j;
            #pragma unroll 4
            for (int k = k0; k < ke; k++, wp += NCOL) {
                u64 w2 = dup2(__ldg(wp));
                const u64* ap = (const u64*)(actT + k * AST + rbase);
                #pragma unroll
                for (int p = 0; p < 8; p++) fma2(acc[p], ap[p], w2);
            }
            // s part (U rows k-256)
            int kb = (k0 > 256) ? k0 : 256;
            const float* up = U + (size_t)(kb - 256) * NCOL + j;
            #pragma unroll 4
            for (int k = kb; k < k1; k++, up += NCOL) {
                u64 w2 = dup2(__ldg(up));
                const u64* ap = (const u64*)(actT + k * AST + rbase);
                #pragma unroll
                for (int p = 0; p < 8; p++) fma2(acc[p], ap[p], w2);
            }
            if (kq > 0) {
                int slot = (kq - 1) * 64 + rb * 32 + lane;
                #pragma unroll
                for (int p = 0; p < 8; p++) {
                    float lo, hi; unpack2(acc[p], lo, hi);
                    red[(2 * p) * 192 + slot]     = lo;
                    red[(2 * p + 1) * 192 + slot] = hi;
                }
            }
            __syncthreads();
            if (kq == 0) {
                float a[16];
                #pragma unroll
                for (int p = 0; p < 8; p++) unpack2(acc[p], a[2 * p], a[2 * p + 1]);
                int slot = rb * 32 + lane;
                #pragma unroll
                for (int pp = 0; pp < 3; pp++)
                    #pragma unroll
                    for (int i = 0; i < 16; i++)
                        a[i] += red[i * 192 + pp * 64 + slot];
                float bias = Bb[j];
                const float* hvp = hvt + (size_t)(row0 + rbase) * NCOL + j;
                if (j < HDIM) {
                    #pragma unroll
                    for (int i = 0; i < 16; i++) {
                        float av = a[i] + bias + hvp[(size_t)i * NCOL];
                        float rv = sigf(av);
                        float sval = actT[(256 + j) * AST + rbase + i];
                        g_rs[(row0 + rbase + i) * HDIM + j] = rv * sval;
                    }
                } else {
                    #pragma unroll
                    for (int i = 0; i < 16; i++) {
                        float av = a[i] + bias + hvp[(size_t)i * NCOL];
                        g_z[(row0 + rbase + i) * HDIM + (j - HDIM)] = sigf(av);
                    }
                }
            }
        }
        // all threads: A1's red reads are done before A2 overwrites red
        __syncthreads();

        //==================== A2: xs pre for j in [1024,1536) ====================
        // 16 cols x (2 row-blocks of 16) x (8-way k-split of 256)
        {
            int ci = tid & 15, rb = (tid >> 4) & 1, kq = tid >> 5;
            int rbase = rb * 16;
            int j = 1024 + kcs + ci;
            u64 acc[8];
            #pragma unroll
            for (int p = 0; p < 8; p++) acc[p] = 0ull;
            int k0 = kq * 32;
            const float* wp = W + (size_t)k0 * NCOL + j;
            #pragma unroll 4
            for (int k = k0; k < k0 + 32; k++, wp += NCOL) {
                u64 w2 = dup2(__ldg(wp));
                const u64* ap = (const u64*)(actT + k * AST + rbase);
                #pragma unroll
                for (int p = 0; p < 8; p++) fma2(acc[p], ap[p], w2);
            }
            if (kq > 0) {
                int slot = (kq - 1) * 32 + rb * 16 + ci;
                #pragma unroll
                for (int p = 0; p < 8; p++) {
                    float lo, hi; unpack2(acc[p], lo, hi);
                    red[(2 * p) * 224 + slot]     = lo;
                    red[(2 * p + 1) * 224 + slot] = hi;
                }
            }
            __syncthreads();
            if (kq == 0) {
                float a[16];
                #pragma unroll
                for (int p = 0; p < 8; p++) unpack2(acc[p], a[2 * p], a[2 * p + 1]);
                int slot = rb * 16 + ci;
                #pragma unroll
                for (int pp = 0; pp < 7; pp++)
                    #pragma unroll
                    for (int i = 0; i < 16; i++)
                        a[i] += red[i * 224 + pp * 32 + slot];
                float bias = Bb[j];
                const float* hvp = hvt + (size_t)(row0 + rbase) * NCOL + j;
                #pragma unroll
                for (int i = 0; i < 16; i++)
                    xs_sh[(rbase + i) * XS_COLS + ci] = a[i] + bias + hvp[(size_t)i * NCOL];
            }
        }
        group_barrier(g, &bar_target);   // r*s, z visible group-wide

        //==================== B: m = (r*s)@U_s, then s_t ====================
        for (int i = tid; i < RG * HDIM; i += NTH) {
            int r = i >> 9, k = i & 511;
            rsT[k * AST + r] = g_rs[(row0 + r) * HDIM + k];
        }
        __syncthreads();
        {
            int ci = tid & 15, rb = (tid >> 4) & 1, kq = tid >> 5;
            int rbase = rb * 16;
            int jcol = 1024 + kcs + ci;
            u64 acc[8];
            #pragma unroll
            for (int p = 0; p < 8; p++) acc[p] = 0ull;
            int k0 = kq * 64;
            const float* up = U + (size_t)k0 * NCOL + jcol;
            #pragma unroll 4
            for (int k = k0; k < k0 + 64; k++, up += NCOL) {
                u64 w2 = dup2(__ldg(up));
                const u64* ap = (const u64*)(rsT + k * AST + rbase);
                #pragma unroll
                for (int p = 0; p < 8; p++) fma2(acc[p], ap[p], w2);
            }
            if (kq > 0) {
                int slot = (kq - 1) * 32 + rb * 16 + ci;
                #pragma unroll
                for (int p = 0; p < 8; p++) {
                    float lo, hi; unpack2(acc[p], lo, hi);
                    red[(2 * p) * 224 + slot]     = lo;
                    red[(2 * p + 1) * 224 + slot] = hi;
                }
            }
            __syncthreads();
            if (kq == 0) {
                float a[16];
                #pragma unroll
                for (int p = 0; p < 8; p++) unpack2(acc[p], a[2 * p], a[2 * p + 1]);
                int slot = rb * 16 + ci;
                #pragma unroll
                for (int pp = 0; pp < 7; pp++)
                    #pragma unroll
                    for (int i = 0; i < 16; i++)
                        a[i] += red[i * 224 + pp * 32 + slot];
                int kglob = kcs + ci;
                #pragma unroll
                for (int i = 0; i < 16; i++) {
                    int rr = rbase + i;
                    float s1 = tanhf(xs_sh[rr * XS_COLS + ci] + a[i]);
                    float zv = g_z[(row0 + rr) * HDIM + kglob];
                    float sold = actT[(256 + kglob) * AST + rr];
                    float snew = (1.0f - zv) * sold + zv * s1;
                    g_s[(row0 + rr) * HDIM + kglob] = snew;
                }
            }
        }
        group_barrier(g, &bar_target);   // s_t visible group-wide

        //==================== C: x_t = tanh(s_t @ Wxo + bx) ====================
        for (int i = tid; i < RG * HDIM; i += NTH) {
            int r = i >> 9, k = i & 511;
            actT[(256 + k) * AST + r] = g_s[(row0 + r) * HDIM + k];
        }
        __syncthreads();
        {
            int ci = tid & 7, rb = (tid >> 3) & 3, kq = tid >> 5;
            int rbase = rb * 8;
            int oc = o0 + ci;
            u64 acc[4];
            #pragma unroll
            for (int p = 0; p < 4; p++) acc[p] = 0ull;
            int k0 = kq * 64;
            const float* wp = Wx + (size_t)k0 * (3 * ODIM) + oc;
            #pragma unroll 4
            for (int k = k0; k < k0 + 64; k++, wp += 3 * ODIM) {
                u64 w2 = dup2(__ldg(wp));
                const u64* ap = (const u64*)(actT + (256 + k) * AST + rbase);
                #pragma unroll
                for (int p = 0; p < 4; p++) fma2(acc[p], ap[p], w2);
            }
            if (kq > 0) {
                int slot = (kq - 1) * 32 + rb * 8 + ci;
                #pragma unroll
                for (int p = 0; p < 4; p++) {
                    float lo, hi; unpack2(acc[p], lo, hi);
                    red[(2 * p) * 224 + slot]     = lo;
                    red[(2 * p + 1) * 224 + slot] = hi;
                }
            }
            __syncthreads();
            if (kq == 0) {
                float a[8];
                #pragma unroll
                for (int p = 0; p < 4; p++) unpack2(acc[p], a[2 * p], a[2 * p + 1]);
                int slot = rb * 8 + ci;
                #pragma unroll
                for (int pp = 0; pp < 7; pp++)
                    #pragma unroll
                    for (int i = 0; i < 8; i++)
                        a[i] += red[i * 224 + pp * 32 + slot];
                float bias = bx[oc];
                #pragma unroll
                for (int i = 0; i < 8; i++) {
                    int rr = rbase + i;
                    float xv = tanhf(a[i] + bias);
                    g_x[(row0 + rr) * ODIM + oc] = xv;
                    out[((size_t)(row0 + rr) * TT + t) * ODIM + oc] = xv;
                }
            }
        }
        group_barrier(g, &bar_target);   // x_t visible group-wide

        // restage x for next step
        for (int i = tid; i < RG * ODIM; i += NTH) {
            int r = i >> 8, k = i & 255;
            actT[k * AST + r] = g_x[(row0 + r) * ODIM + k];
        }
        __syncthreads();
    }
}

// ---------------- launch ----------------
extern "C" void kernel_launch(void* const* d_in, const int* in_sizes, int n_in,
                              void* d_out, int out_size) {
    const float* H  = (const float*)d_in[0];
    const float* W  = (const float*)d_in[1];
    const float* Bb = (const float*)d_in[2];
    const float* U  = (const float*)d_in[3];
    const float* Wx = (const float*)d_in[4];
    const float* bx = (const float*)d_in[5];
    const float* Vr = (const float*)d_in[6];
    const float* Vz = (const float*)d_in[7];
    const float* Vs = (const float*)d_in[8];
    float* out = (float*)d_out;

    const size_t smem_bytes = (size_t)SM_TOTAL * sizeof(float);  // 190,464 B
    cudaFuncSetAttribute(recur_kernel, cudaFuncAttributeMaxDynamicSharedMemorySize,
                         (int)smem_bytes);

    init_kernel<<<256, 256>>>(H);
    hv_gemm<<<dim3(12, 512), 256>>>(H, Vr, Vz, Vs);
    recur_kernel<<<NCTA, NTH, smem_bytes>>>(W, Bb, U, Wx, bx, out);
}

// round 5
// speedup vs baseline: 1.7536x; 1.7536x over previous
#include <cuda_runtime.h>
#include <math.h>
#include <stdint.h>

// Problem dims
#define BATCH 128
#define TT    512
#define DIM   512
#define HDIM  512
#define ODIM  256
#define NCOL  1536   // 3*HDIM

// Recurrence partition: 4 row-groups x 32 rows; 32 CTAs per group (column slices)
#define NG  4
#define RG  32
#define NC  32
#define NCTA (NG*NC)
#define NTH 512      // 16 warps -> 4 per SMSP for latency hiding

#define RZ_COLS 32   // pre-activation columns in [0,1024) per CTA
#define XS_COLS 16   // hdim slice of [1024,1536) per CTA
#define XO_COLS 8    // output columns of Wxo per CTA

// Shared memory layout (floats). AST=34: even (8B-aligned u64 loads), 2-way
// conflict max on transposed staging stores.
#define AST      34
#define SM_ACT   0
#define SM_RS    (768*AST)                 // 26112
#define SM_XS    (SM_RS + 512*AST)         // 43520
#define SM_RED   (SM_XS + RG*XS_COLS)      // 44032
#define SM_TOTAL (SM_RED + 7168)           // 51200 floats = 204800 bytes

typedef unsigned long long u64;

__device__ __forceinline__ u64 pack2(float lo, float hi) {
    u64 r; asm("mov.b64 %0,{%1,%2};" : "=l"(r) : "f"(lo), "f"(hi)); return r;
}
__device__ __forceinline__ void unpack2(u64 v, float& lo, float& hi) {
    asm("mov.b64 {%0,%1},%2;" : "=f"(lo), "=f"(hi) : "l"(v));
}
__device__ __forceinline__ void fma2(u64& d, u64 a, u64 b) {
    asm("fma.rn.f32x2 %0,%1,%2,%0;" : "+l"(d) : "l"(a), "l"(b));
}
__device__ __forceinline__ u64 dup2(float w) { return pack2(w, w); }

// ---------------- device scratch ----------------
__device__ float g_hV[(size_t)TT * BATCH * NCOL];  // precomputed hV[t][b][j]
__device__ float g_s [BATCH * HDIM];
__device__ float g_x [BATCH * ODIM];
__device__ float g_rs[BATCH * HDIM];
__device__ float g_z [BATCH * HDIM];
__device__ unsigned g_bar[NG];

__device__ __forceinline__ float sigf(float x) { return 1.0f / (1.0f + expf(-x)); }

// ---------------- hV GEMM (f32x2): hV[t][b][j] = sum_d H[b][511-t][d]*Vcat[d][j] ----------------
#define GT_N 128
#define GT_K 8
__global__ void __launch_bounds__(256, 2)
hv_gemm(const float* __restrict__ H,
        const float* __restrict__ Vr,
        const float* __restrict__ Vz,
        const float* __restrict__ Vs) {
    // reset the recurrence barrier counters (stream-ordered before recur)
    if (blockIdx.x == 0 && blockIdx.y == 0 && threadIdx.x < NG)
        g_bar[threadIdx.x] = 0u;

    int t  = blockIdx.y;
    int jt = blockIdx.x;
    const float* V = (jt < 4) ? Vr : ((jt < 8) ? Vz : Vs);
    int col0 = (jt & 3) * GT_N;
    const float* A = H + (size_t)(TT - 1 - t) * DIM;

    __shared__ float Ash[GT_K][BATCH + 4];
    __shared__ float Bsh[GT_K][GT_N];

    int tx = threadIdx.x & 15, ty = threadIdx.x >> 4;
    u64 acc[4][8];
    #pragma unroll
    for (int i = 0; i < 4; i++)
        #pragma unroll
        for (int j = 0; j < 8; j++) acc[i][j] = 0ull;

    for (int k0 = 0; k0 < DIM; k0 += GT_K) {
        for (int i = threadIdx.x; i < BATCH * GT_K; i += 256) {
            int bb = i >> 3, dd = i & 7;
            Ash[dd][bb] = A[(size_t)bb * (TT * DIM) + k0 + dd];
        }
        for (int i = threadIdx.x; i < GT_K * GT_N; i += 256) {
            int dd = i >> 7, jj = i & 127;
            Bsh[dd][jj] = V[(size_t)(k0 + dd) * HDIM + col0 + jj];
        }
        __syncthreads();
        #pragma unroll
        for (int kk = 0; kk < GT_K; kk++) {
            const u64* ap0 = (const u64*)&Ash[kk][ty * 4];
            const u64* ap1 = (const u64*)&Ash[kk][64 + ty * 4];
            u64 av[4] = { ap0[0], ap0[1], ap1[0], ap1[1] };
            u64 bv[8];
            #pragma unroll
            for (int j = 0; j < 8; j++) {
                float b = (j < 4) ? Bsh[kk][tx * 4 + j] : Bsh[kk][64 + tx * 4 + (j - 4)];
                bv[j] = dup2(b);
            }
            #pragma unroll
            for (int i = 0; i < 4; i++)
                #pragma unroll
                for (int j = 0; j < 8; j++)
                    fma2(acc[i][j], av[i], bv[j]);
        }
        __syncthreads();
    }
    float* outp = g_hV + (size_t)t * BATCH * NCOL + jt * GT_N;
    int rowb[4] = { ty * 4, ty * 4 + 2, 64 + ty * 4, 64 + ty * 4 + 2 };
    #pragma unroll
    for (int i = 0; i < 4; i++)
        #pragma unroll
        for (int j = 0; j < 8; j++) {
            float lo, hi; unpack2(acc[i][j], lo, hi);
            int jc = (j < 4) ? (tx * 4 + j) : (64 + tx * 4 + (j - 4));
            outp[(size_t)rowb[i] * NCOL + jc]       = lo;
            outp[(size_t)(rowb[i] + 1) * NCOL + jc] = hi;
        }
}

// ---------------- group barrier (acquire/release, no MEMBAR.ALL) ----------------
__device__ __forceinline__ void group_barrier(int g, unsigned* target) {
    __syncthreads();
    if (threadIdx.x == 0) {
        unsigned tg = (*target += NC);
        asm volatile("red.release.gpu.global.add.u32 [%0], 1;"
                     :: "l"(&g_bar[g]) : "memory");
        unsigned v;
        do {
            asm volatile("ld.acquire.gpu.global.u32 %0, [%1];"
                         : "=r"(v) : "l"(&g_bar[g]) : "memory");
        } while (v < tg);
    }
    __syncthreads();
}

// ---------------- persistent recurrence kernel: 128 CTAs x 512 threads ----------------
__global__ void __launch_bounds__(NTH, 1)
recur_kernel(const float* __restrict__ H,   // for x0
             const float* __restrict__ W,   // [256][1536]
             const float* __restrict__ Bb,  // [1536]
             const float* __restrict__ U,   // [512][1536]
             const float* __restrict__ Wx,  // [512][768], Wxo = cols [0,256)
             const float* __restrict__ bx,  // [256]
             float* __restrict__ out)       // [128][512][256]
{
    extern __shared__ float sm[];
    float* actT  = sm + SM_ACT;   // [768][34] transposed: rows 0..255 x, 256..767 s
    float* rsT   = sm + SM_RS;    // [512][34] transposed r*s
    float* xs_sh = sm + SM_XS;    // [32][16]
    float* red   = sm + SM_RED;   // k-split reduction scratch (7168 floats)

    const int cta = blockIdx.x;
    const int g   = cta >> 5;
    const int c   = cta & 31;
    const int tid = threadIdx.x;
    const int row0 = g * RG;

    const int jrz = c * RZ_COLS;
    const int kcs = c * XS_COLS;
    const int o0  = c * XO_COLS;

    unsigned bar_target = 0;

    // Initial staging: x0 directly from H (no init kernel), s = 0
    for (int i = tid; i < RG * ODIM; i += NTH) {
        int r = i >> 8, k = i & 255;
        const float* h = H + ((size_t)(row0 + r) * TT + (TT - 1)) * DIM;
        actT[k * AST + r] = h[k] + h[k + ODIM];
    }
    for (int i = tid; i < RG * HDIM; i += NTH) {
        int r = i >> 9, k = i & 511;
        actT[(256 + k) * AST + r] = 0.0f;
    }
    __syncthreads();

    for (int t = 0; t < TT; t++) {
        const float* hvt = g_hV + (size_t)t * BATCH * NCOL;

        //==================== A1: pre for j in [0,1024) ====================
        // 32 cols x (2 row-blocks of 16) x (8-way k-split of 768, 96 each)
        {
            int lane = tid & 31;
            int wrp  = tid >> 5;
            int rb = wrp & 1, kq = wrp >> 1;
            int rbase = rb * 16;
            int j = jrz + lane;

            // prefetch epilogue hV (overlaps with the GEMV below)
            float hvv[16];
            if (kq == 0) {
                const float* hvp = hvt + (size_t)(row0 + rbase) * NCOL + j;
                #pragma unroll
                for (int i = 0; i < 16; i++) hvv[i] = __ldg(hvp + (size_t)i * NCOL);
            }

            u64 acc[8];
            #pragma unroll
            for (int p = 0; p < 8; p++) acc[p] = 0ull;

            int k0 = kq * 96, k1 = k0 + 96;
            int ke = (k1 < 256) ? k1 : 256;          // x part (W rows)
            const float* wp = W + (size_t)k0 * NCOL + j;
            #pragma unroll 4
            for (int k = k0; k < ke; k++, wp += NCOL) {
                u64 w2 = dup2(__ldg(wp));
                const u64* ap = (const u64*)(actT + k * AST + rbase);
                #pragma unroll
                for (int p = 0; p < 8; p++) fma2(acc[p], ap[p], w2);
            }
            int kb = (k0 > 256) ? k0 : 256;          // s part (U rows)
            const float* up = U + (size_t)(kb - 256) * NCOL + j;
            #pragma unroll 4
            for (int k = kb; k < k1; k++, up += NCOL) {
                u64 w2 = dup2(__ldg(up));
                const u64* ap = (const u64*)(actT + k * AST + rbase);
                #pragma unroll
                for (int p = 0; p < 8; p++) fma2(acc[p], ap[p], w2);
            }
            if (kq > 0) {
                int slot = (kq - 1) * 64 + rb * 32 + lane;
                #pragma unroll
                for (int p = 0; p < 8; p++) {
                    float lo, hi; unpack2(acc[p], lo, hi);
                    red[(2 * p) * 448 + slot]     = lo;
                    red[(2 * p + 1) * 448 + slot] = hi;
                }
            }
            __syncthreads();
            if (kq == 0) {
                float a[16];
                #pragma unroll
                for (int p = 0; p < 8; p++) unpack2(acc[p], a[2 * p], a[2 * p + 1]);
                int slot = rb * 32 + lane;
                #pragma unroll
                for (int pp = 0; pp < 7; pp++)
                    #pragma unroll
                    for (int i = 0; i < 16; i++)
                        a[i] += red[i * 448 + pp * 64 + slot];
                float bias = Bb[j];
                if (j < HDIM) {
                    #pragma unroll
                    for (int i = 0; i < 16; i++) {
                        float av = a[i] + bias + hvv[i];
                        float rv = sigf(av);
                        float sval = actT[(256 + j) * AST + rbase + i];
                        g_rs[(row0 + rbase + i) * HDIM + j] = rv * sval;
                    }
                } else {
                    #pragma unroll
                    for (int i = 0; i < 16; i++) {
                        float av = a[i] + bias + hvv[i];
                        g_z[(row0 + rbase + i) * HDIM + (j - HDIM)] = sigf(av);
                    }
                }
            }
        }
        __syncthreads();   // A1 red reads done before A2 overwrites red

        //==================== A2: xs pre for j in [1024,1536) ====================
        // 16 cols x (4 row-blocks of 8) x (8-way k-split of 256, 32 each)
        {
            int ci = tid & 15, rb = (tid >> 4) & 3, kq = tid >> 6;
            int rbase = rb * 8;
            int j = 1024 + kcs + ci;

            float hvv[8];
            if (kq == 0) {
                const float* hvp = hvt + (size_t)(row0 + rbase) * NCOL + j;
                #pragma unroll
                for (int i = 0; i < 8; i++) hvv[i] = __ldg(hvp + (size_t)i * NCOL);
            }

            u64 acc[4];
            #pragma unroll
            for (int p = 0; p < 4; p++) acc[p] = 0ull;
            int k0 = kq * 32;
            const float* wp = W + (size_t)k0 * NCOL + j;
            #pragma unroll 4
            for (int k = k0; k < k0 + 32; k++, wp += NCOL) {
                u64 w2 = dup2(__ldg(wp));
                const u64* ap = (const u64*)(actT + k * AST + rbase);
                #pragma unroll
                for (int p = 0; p < 4; p++) fma2(acc[p], ap[p], w2);
            }
            if (kq > 0) {
                int slot = (kq - 1) * 64 + rb * 16 + ci;
                #pragma unroll
                for (int p = 0; p < 4; p++) {
                    float lo, hi; unpack2(acc[p], lo, hi);
                    red[(2 * p) * 448 + slot]     = lo;
                    red[(2 * p + 1) * 448 + slot] = hi;
                }
            }
            __syncthreads();
            if (kq == 0) {
                float a[8];
                #pragma unroll
                for (int p = 0; p < 4; p++) unpack2(acc[p], a[2 * p], a[2 * p + 1]);
                int slot = rb * 16 + ci;
                #pragma unroll
                for (int pp = 0; pp < 7; pp++)
                    #pragma unroll
                    for (int i = 0; i < 8; i++)
                        a[i] += red[i * 448 + pp * 64 + slot];
                float bias = Bb[j];
                #pragma unroll
                for (int i = 0; i < 8; i++)
                    xs_sh[(rbase + i) * XS_COLS + ci] = a[i] + bias + hvv[i];
            }
        }
        group_barrier(g, &bar_target);   // r*s, z visible group-wide

        //==================== B: m = (r*s)@U_s, then s_t ====================
        for (int i = tid; i < RG * HDIM; i += NTH) {
            int r = i >> 9, k = i & 511;
            rsT[k * AST + r] = g_rs[(row0 + r) * HDIM + k];
        }
        __syncthreads();
        {
            int ci = tid & 15, rb = (tid >> 4) & 3, kq = tid >> 6;
            int rbase = rb * 8;
            int jcol = 1024 + kcs + ci;
            int kglob = kcs + ci;

            float zv[8];
            if (kq == 0) {
                #pragma unroll
                for (int i = 0; i < 8; i++)
                    zv[i] = g_z[(row0 + rbase + i) * HDIM + kglob];
            }

            u64 acc[4];
            #pragma unroll
            for (int p = 0; p < 4; p++) acc[p] = 0ull;
            int k0 = kq * 64;
            const float* up = U + (size_t)k0 * NCOL + jcol;
            #pragma unroll 4
            for (int k = k0; k < k0 + 64; k++, up += NCOL) {
                u64 w2 = dup2(__ldg(up));
                const u64* ap = (const u64*)(rsT + k * AST + rbase);
                #pragma unroll
                for (int p = 0; p < 4; p++) fma2(acc[p], ap[p], w2);
            }
            if (kq > 0) {
                int slot = (kq - 1) * 64 + rb * 16 + ci;
                #pragma unroll
                for (int p = 0; p < 4; p++) {
                    float lo, hi; unpack2(acc[p], lo, hi);
                    red[(2 * p) * 448 + slot]     = lo;
                    red[(2 * p + 1) * 448 + slot] = hi;
                }
            }
            __syncthreads();
            if (kq == 0) {
                float a[8];
                #pragma unroll
                for (int p = 0; p < 4; p++) unpack2(acc[p], a[2 * p], a[2 * p + 1]);
                int slot = rb * 16 + ci;
                #pragma unroll
                for (int pp = 0; pp < 7; pp++)
                    #pragma unroll
                    for (int i = 0; i < 8; i++)
                        a[i] += red[i * 448 + pp * 64 + slot];
                #pragma unroll
                for (int i = 0; i < 8; i++) {
                    int rr = rbase + i;
                    float s1 = tanhf(xs_sh[rr * XS_COLS + ci] + a[i]);
                    float sold = actT[(256 + kglob) * AST + rr];
                    float snew = (1.0f - zv[i]) * sold + zv[i] * s1;
                    g_s[(row0 + rr) * HDIM + kglob] = snew;
                }
            }
        }
        group_barrier(g, &bar_target);   // s_t visible group-wide

        //==================== C: x_t = tanh(s_t @ Wxo + bx) ====================
        for (int i = tid; i < RG * HDIM; i += NTH) {
            int r = i >> 9, k = i & 511;
            actT[(256 + k) * AST + r] = g_s[(row0 + r) * HDIM + k];
        }
        __syncthreads();
        {
            int ci = tid & 7, rb = (tid >> 3) & 7, kq = tid >> 6;
            int rbase = rb * 4;
            int oc = o0 + ci;
            u64 acc[2];
            #pragma unroll
            for (int p = 0; p < 2; p++) acc[p] = 0ull;
            int k0 = kq * 64;
            const float* wp = Wx + (size_t)k0 * (3 * ODIM) + oc;
            #pragma unroll 4
            for (int k = k0; k < k0 + 64; k++, wp += 3 * ODIM) {
                u64 w2 = dup2(__ldg(wp));
                const u64* ap = (const u64*)(actT + (256 + k) * AST + rbase);
                #pragma unroll
                for (int p = 0; p < 2; p++) fma2(acc[p], ap[p], w2);
            }
            if (kq > 0) {
                int slot = (kq - 1) * 64 + rb * 8 + ci;
                #pragma unroll
                for (int p = 0; p < 2; p++) {
                    float lo, hi; unpack2(acc[p], lo, hi);
                    red[(2 * p) * 448 + slot]     = lo;
                    red[(2 * p + 1) * 448 + slot] = hi;
                }
            }
            __syncthreads();
            if (kq == 0) {
                float a[4];
                #pragma unroll
                for (int p = 0; p < 2; p++) unpack2(acc[p], a[2 * p], a[2 * p + 1]);
                int slot = rb * 8 + ci;
                #pragma unroll
                for (int pp = 0; pp < 7; pp++)
                    #pragma unroll
                    for (int i = 0; i < 4; i++)
                        a[i] += red[i * 448 + pp * 64 + slot];
                float bias = bx[oc];
                #pragma unroll
                for (int i = 0; i < 4; i++) {
                    int rr = rbase + i;
                    float xv = tanhf(a[i] + bias);
                    g_x[(row0 + rr) * ODIM + oc] = xv;
                    out[((size_t)(row0 + rr) * TT + t) * ODIM + oc] = xv;
                }
            }
        }
        group_barrier(g, &bar_target);   // x_t visible group-wide

        // restage x for next step
        for (int i = tid; i < RG * ODIM; i += NTH) {
            int r = i >> 8, k = i & 255;
            actT[k * AST + r] = g_x[(row0 + r) * ODIM + k];
        }
        __syncthreads();
    }
}

// ---------------- launch ----------------
extern "C" void kernel_launch(void* const* d_in, const int* in_sizes, int n_in,
                              void* d_out, int out_size) {
    const float* H  = (const float*)d_in[0];
    const float* W  = (const float*)d_in[1];
    const float* Bb = (const float*)d_in[2];
    const float* U  = (const float*)d_in[3];
    const float* Wx = (const float*)d_in[4];
    const float* bx = (const float*)d_in[5];
    const float* Vr = (const float*)d_in[6];
    const float* Vz = (const float*)d_in[7];
    const float* Vs = (const float*)d_in[8];
    float* out = (float*)d_out;

    const size_t smem_bytes = (size_t)SM_TOTAL * sizeof(float);  // 204,800 B
    cudaFuncSetAttribute(recur_kernel, cudaFuncAttributeMaxDynamicSharedMemorySize,
                         (int)smem_bytes);

    hv_gemm<<<dim3(12, 512), 256>>>(H, Vr, Vz, Vs);
    recur_kernel<<<NCTA, NTH, smem_bytes>>>(H, W, Bb, U, Wx, bx, out);
}

// round 6
// speedup vs baseline: 2.0819x; 1.1872x over previous
#include <cuda_runtime.h>
#include <math.h>
#include <stdint.h>

// Problem dims
#define BATCH 128
#define TT    512
#define DIM   512
#define HDIM  512
#define ODIM  256
#define NCOL  1536   // 3*HDIM

// Recurrence partition: 4 row-groups x 32 rows; 32 CTAs per group (column slices)
#define NG  4
#define RG  32
#define NC  32
#define NCTA (NG*NC)
#define NTH 512      // 16 warps

#define RZ_COLS 32   // pre-activation columns in [0,1024) per CTA
#define XS_COLS 16   // hdim slice of [1024,1536) per CTA
#define XO_COLS 8    // output columns of Wxo per CTA

// Shared memory layout (floats). AST=34 (even -> 8B-aligned u64 rows).
#define AST      34
#define SM_ACT   0
#define SM_RS    (768*AST)                 // 26112
#define SM_XS    (SM_RS + 512*AST)         // 43520
#define SM_RED   (SM_XS + RG*XS_COLS)      // 44032 (even -> u64-aligned)
#define SM_TOTAL (SM_RED + 7680)           // 51712 floats = 206848 bytes

typedef unsigned long long u64;

__device__ __forceinline__ u64 pack2(float lo, float hi) {
    u64 r; asm("mov.b64 %0,{%1,%2};" : "=l"(r) : "f"(lo), "f"(hi)); return r;
}
__device__ __forceinline__ void unpack2(u64 v, float& lo, float& hi) {
    asm("mov.b64 {%0,%1},%2;" : "=f"(lo), "=f"(hi) : "l"(v));
}
__device__ __forceinline__ void fma2(u64& d, u64 a, u64 b) {
    asm("fma.rn.f32x2 %0,%1,%2,%0;" : "+l"(d) : "l"(a), "l"(b));
}
__device__ __forceinline__ u64 add2(u64 a, u64 b) {
    u64 r; asm("add.rn.f32x2 %0,%1,%2;" : "=l"(r) : "l"(a), "l"(b)); return r;
}
__device__ __forceinline__ u64 dup2(float w) { return pack2(w, w); }

// ---------------- device scratch ----------------
__device__ float g_hV[(size_t)TT * BATCH * NCOL];  // precomputed hV[t][b][j]
__device__ float g_s [BATCH * HDIM];
__device__ float g_x [BATCH * ODIM];
__device__ float g_rs[BATCH * HDIM];
__device__ float g_z [BATCH * HDIM];
__device__ unsigned g_bar[NG];

__device__ __forceinline__ float sigf(float x) { return 1.0f / (1.0f + expf(-x)); }

// ---------------- hV GEMM (f32x2): hV[t][b][j] = sum_d H[b][511-t][d]*Vcat[d][j] ----------------
#define GT_N 128
#define GT_K 8
__global__ void __launch_bounds__(256, 2)
hv_gemm(const float* __restrict__ H,
        const float* __restrict__ Vr,
        const float* __restrict__ Vz,
        const float* __restrict__ Vs) {
    if (blockIdx.x == 0 && blockIdx.y == 0 && threadIdx.x < NG)
        g_bar[threadIdx.x] = 0u;

    int t  = blockIdx.y;
    int jt = blockIdx.x;
    const float* V = (jt < 4) ? Vr : ((jt < 8) ? Vz : Vs);
    int col0 = (jt & 3) * GT_N;
    const float* A = H + (size_t)(TT - 1 - t) * DIM;

    __shared__ float Ash[GT_K][BATCH + 4];
    __shared__ float Bsh[GT_K][GT_N];

    int tx = threadIdx.x & 15, ty = threadIdx.x >> 4;
    u64 acc[4][8];
    #pragma unroll
    for (int i = 0; i < 4; i++)
        #pragma unroll
        for (int j = 0; j < 8; j++) acc[i][j] = 0ull;

    for (int k0 = 0; k0 < DIM; k0 += GT_K) {
        for (int i = threadIdx.x; i < BATCH * GT_K; i += 256) {
            int bb = i >> 3, dd = i & 7;
            Ash[dd][bb] = A[(size_t)bb * (TT * DIM) + k0 + dd];
        }
        for (int i = threadIdx.x; i < GT_K * GT_N; i += 256) {
            int dd = i >> 7, jj = i & 127;
            Bsh[dd][jj] = V[(size_t)(k0 + dd) * HDIM + col0 + jj];
        }
        __syncthreads();
        #pragma unroll
        for (int kk = 0; kk < GT_K; kk++) {
            const u64* ap0 = (const u64*)&Ash[kk][ty * 4];
            const u64* ap1 = (const u64*)&Ash[kk][64 + ty * 4];
            u64 av[4] = { ap0[0], ap0[1], ap1[0], ap1[1] };
            u64 bv[8];
            #pragma unroll
            for (int j = 0; j < 8; j++) {
                float b = (j < 4) ? Bsh[kk][tx * 4 + j] : Bsh[kk][64 + tx * 4 + (j - 4)];
                bv[j] = dup2(b);
            }
            #pragma unroll
            for (int i = 0; i < 4; i++)
                #pragma unroll
                for (int j = 0; j < 8; j++)
                    fma2(acc[i][j], av[i], bv[j]);
        }
        __syncthreads();
    }
    float* outp = g_hV + (size_t)t * BATCH * NCOL + jt * GT_N;
    int rowb[4] = { ty * 4, ty * 4 + 2, 64 + ty * 4, 64 + ty * 4 + 2 };
    #pragma unroll
    for (int i = 0; i < 4; i++)
        #pragma unroll
        for (int j = 0; j < 8; j++) {
            float lo, hi; unpack2(acc[i][j], lo, hi);
            int jc = (j < 4) ? (tx * 4 + j) : (64 + tx * 4 + (j - 4));
            outp[(size_t)rowb[i] * NCOL + jc]       = lo;
            outp[(size_t)(rowb[i] + 1) * NCOL + jc] = hi;
        }
}

// ---------------- group barrier (acquire/release) ----------------
__device__ __forceinline__ void group_barrier(int g, unsigned* target) {
    __syncthreads();
    if (threadIdx.x == 0) {
        unsigned tg = (*target += NC);
        asm volatile("red.release.gpu.global.add.u32 [%0], 1;"
                     :: "l"(&g_bar[g]) : "memory");
        unsigned v;
        do {
            asm volatile("ld.acquire.gpu.global.u32 %0, [%1];"
                         : "=r"(v) : "l"(&g_bar[g]) : "memory");
        } while (v < tg);
    }
    __syncthreads();
}

// ---------------- persistent recurrence kernel: 128 CTAs x 512 threads ----------------
__global__ void __launch_bounds__(NTH, 1)
recur_kernel(const float* __restrict__ H,   // for x0
             const float* __restrict__ W,   // [256][1536]
             const float* __restrict__ Bb,  // [1536]
             const float* __restrict__ U,   // [512][1536]
             const float* __restrict__ Wx,  // [512][768], Wxo = cols [0,256)
             const float* __restrict__ bx,  // [256]
             float* __restrict__ out)       // [128][512][256]
{
    extern __shared__ float sm[];
    float* actT  = sm + SM_ACT;   // [768][34] transposed: rows 0..255 x, 256..767 s
    float* rsT   = sm + SM_RS;    // [512][34] transposed r*s
    float* xs_sh = sm + SM_XS;    // [32][16]
    u64*   red64 = (u64*)(sm + SM_RED);  // k-split partials as packed pairs

    const int cta = blockIdx.x;
    const int g   = cta >> 5;
    const int c   = cta & 31;
    const int tid = threadIdx.x;
    const int row0 = g * RG;

    const int jrz = c * RZ_COLS;
    const int kcs = c * XS_COLS;
    const int o0  = c * XO_COLS;

    const int lane = tid & 31;
    const int wrp  = tid >> 5;

    unsigned bar_target = 0;

    // Initial staging: x0 directly from H, s = 0
    for (int i = tid; i < RG * ODIM; i += NTH) {
        int r = i >> 8, k = i & 255;
        const float* h = H + ((size_t)(row0 + r) * TT + (TT - 1)) * DIM;
        actT[k * AST + r] = h[k] + h[k + ODIM];
    }
    for (int i = tid; i < RG * HDIM / 2; i += NTH) {
        int q = i >> 9, k = i & 511;
        *(u64*)(actT + (256 + k) * AST + 2 * q) = 0ull;
    }
    __syncthreads();

    for (int t = 0; t < TT; t++) {
        const float* hvt = g_hV + (size_t)t * BATCH * NCOL;

        //==================== A1: pre for j in [0,1024) ====================
        // warp = ch(2 col-halves of 16) x kq(8-way k-split of 768)
        // lane = cg(4 col-groups of 4) x rg(8 row-groups of 4)
        {
            int ch = wrp & 1, kq = wrp >> 1;
            int cg = lane & 3, rg = lane >> 2;
            int jl = ch * 16 + cg * 4;
            int j0 = jrz + jl;
            int rbase = rg * 4;

            float4 hv4[4]; float4 bb4;
            if (kq == 0) {
                const float* hvp = hvt + (size_t)(row0 + rbase) * NCOL + j0;
                #pragma unroll
                for (int r = 0; r < 4; r++) hv4[r] = *(const float4*)(hvp + (size_t)r * NCOL);
                bb4 = *(const float4*)(Bb + j0);
            }

            u64 acc[4][2];
            #pragma unroll
            for (int ci = 0; ci < 4; ci++) { acc[ci][0] = 0ull; acc[ci][1] = 0ull; }

            int k0 = kq * 96, k1 = k0 + 96;
            int ke = (k1 < 256) ? k1 : 256;          // x part (W rows)
            const float* wp = W + (size_t)k0 * NCOL + j0;
            #pragma unroll 8
            for (int k = k0; k < ke; k++, wp += NCOL) {
                float4 wv = *(const float4*)wp;
                const u64* ap = (const u64*)(actT + k * AST + rbase);
                u64 a0 = ap[0], a1 = ap[1];
                u64 w0 = dup2(wv.x), w1 = dup2(wv.y), w2 = dup2(wv.z), w3 = dup2(wv.w);
                fma2(acc[0][0], a0, w0); fma2(acc[0][1], a1, w0);
                fma2(acc[1][0], a0, w1); fma2(acc[1][1], a1, w1);
                fma2(acc[2][0], a0, w2); fma2(acc[2][1], a1, w2);
                fma2(acc[3][0], a0, w3); fma2(acc[3][1], a1, w3);
            }
            int kb = (k0 > 256) ? k0 : 256;          // s part (U rows)
            const float* up = U + (size_t)(kb - 256) * NCOL + j0;
            #pragma unroll 8
            for (int k = kb; k < k1; k++, up += NCOL) {
                float4 wv = *(const float4*)up;
                const u64* ap = (const u64*)(actT + k * AST + rbase);
                u64 a0 = ap[0], a1 = ap[1];
                u64 w0 = dup2(wv.x), w1 = dup2(wv.y), w2 = dup2(wv.z), w3 = dup2(wv.w);
                fma2(acc[0][0], a0, w0); fma2(acc[0][1], a1, w0);
                fma2(acc[1][0], a0, w1); fma2(acc[1][1], a1, w1);
                fma2(acc[2][0], a0, w2); fma2(acc[2][1], a1, w2);
                fma2(acc[3][0], a0, w3); fma2(acc[3][1], a1, w3);
            }
            if (kq > 0) {
                int base = (kq - 1) * 512;
                #pragma unroll
                for (int ci = 0; ci < 4; ci++)
                    #pragma unroll
                    for (int p = 0; p < 2; p++) {
                        int sidx = (jl + ci) * 16 + ((rg * 2 + p + cg * 4) & 15);
                        red64[base + sidx] = acc[ci][p];
                    }
            }
            __syncthreads();
            if (kq == 0) {
                #pragma unroll
                for (int l = 0; l < 7; l++)
                    #pragma unroll
                    for (int ci = 0; ci < 4; ci++)
                        #pragma unroll
                        for (int p = 0; p < 2; p++) {
                            int sidx = (jl + ci) * 16 + ((rg * 2 + p + cg * 4) & 15);
                            acc[ci][p] = add2(acc[ci][p], red64[l * 512 + sidx]);
                        }
                float bbv[4] = { bb4.x, bb4.y, bb4.z, bb4.w };
                float hvv[4][4];
                #pragma unroll
                for (int r = 0; r < 4; r++) {
                    hvv[r][0] = hv4[r].x; hvv[r][1] = hv4[r].y;
                    hvv[r][2] = hv4[r].z; hvv[r][3] = hv4[r].w;
                }
                if (jrz < HDIM) {          // whole CTA is r-gate (c < 16)
                    #pragma unroll
                    for (int ci = 0; ci < 4; ci++) {
                        int j = j0 + ci;
                        #pragma unroll
                        for (int p = 0; p < 2; p++) {
                            float lo, hi; unpack2(acc[ci][p], lo, hi);
                            float a0 = lo + bbv[ci] + hvv[2 * p][ci];
                            float a1 = hi + bbv[ci] + hvv[2 * p + 1][ci];
                            int rr = rbase + 2 * p;
                            float s0 = actT[(256 + j) * AST + rr];
                            float s1v = actT[(256 + j) * AST + rr + 1];
                            g_rs[(row0 + rr) * HDIM + j]     = sigf(a0) * s0;
                            g_rs[(row0 + rr + 1) * HDIM + j] = sigf(a1) * s1v;
                        }
                    }
                } else {                   // whole CTA is z-gate
                    #pragma unroll
                    for (int ci = 0; ci < 4; ci++) {
                        int j = j0 + ci - HDIM;
                        #pragma unroll
                        for (int p = 0; p < 2; p++) {
                            float lo, hi; unpack2(acc[ci][p], lo, hi);
                            float a0 = lo + bbv[ci] + hvv[2 * p][ci];
                            float a1 = hi + bbv[ci] + hvv[2 * p + 1][ci];
                            int rr = rbase + 2 * p;
                            g_z[(row0 + rr) * HDIM + j]     = sigf(a0);
                            g_z[(row0 + rr + 1) * HDIM + j] = sigf(a1);
                        }
                    }
                }
            }
        }
        __syncthreads();   // A1 red reads done before A2 overwrites red

        //==================== A2: xs pre for j in [1024,1536), K=256 ====================
        // warp = kq(16-way split of 256); lane = cg(4) x rg(8)
        {
            int kq = wrp;
            int cg = lane & 3, rg = lane >> 2;
            int jl = cg * 4;
            int j0 = 1024 + kcs + jl;
            int rbase = rg * 4;

            float4 hv4[4]; float4 bb4;
            if (kq == 0) {
                const float* hvp = hvt + (size_t)(row0 + rbase) * NCOL + j0;
                #pragma unroll
                for (int r = 0; r < 4; r++) hv4[r] = *(const float4*)(hvp + (size_t)r * NCOL);
                bb4 = *(const float4*)(Bb + j0);
            }

            u64 acc[4][2];
            #pragma unroll
            for (int ci = 0; ci < 4; ci++) { acc[ci][0] = 0ull; acc[ci][1] = 0ull; }

            int k0 = kq * 16;
            const float* wp = W + (size_t)k0 * NCOL + j0;
            #pragma unroll 8
            for (int k = k0; k < k0 + 16; k++, wp += NCOL) {
                float4 wv = *(const float4*)wp;
                const u64* ap = (const u64*)(actT + k * AST + rbase);
                u64 a0 = ap[0], a1 = ap[1];
                u64 w0 = dup2(wv.x), w1 = dup2(wv.y), w2 = dup2(wv.z), w3 = dup2(wv.w);
                fma2(acc[0][0], a0, w0); fma2(acc[0][1], a1, w0);
                fma2(acc[1][0], a0, w1); fma2(acc[1][1], a1, w1);
                fma2(acc[2][0], a0, w2); fma2(acc[2][1], a1, w2);
                fma2(acc[3][0], a0, w3); fma2(acc[3][1], a1, w3);
            }
            if (kq > 0) {
                int base = (kq - 1) * 256;
                #pragma unroll
                for (int ci = 0; ci < 4; ci++)
                    #pragma unroll
                    for (int p = 0; p < 2; p++) {
                        int sidx = (jl + ci) * 16 + ((rg * 2 + p + cg * 4) & 15);
                        red64[base + sidx] = acc[ci][p];
                    }
            }
            __syncthreads();
            if (kq == 0) {
                #pragma unroll
                for (int l = 0; l < 15; l++)
                    #pragma unroll
                    for (int ci = 0; ci < 4; ci++)
                        #pragma unroll
                        for (int p = 0; p < 2; p++) {
                            int sidx = (jl + ci) * 16 + ((rg * 2 + p + cg * 4) & 15);
                            acc[ci][p] = add2(acc[ci][p], red64[l * 256 + sidx]);
                        }
                float bbv[4] = { bb4.x, bb4.y, bb4.z, bb4.w };
                float hvv[4][4];
                #pragma unroll
                for (int r = 0; r < 4; r++) {
                    hvv[r][0] = hv4[r].x; hvv[r][1] = hv4[r].y;
                    hvv[r][2] = hv4[r].z; hvv[r][3] = hv4[r].w;
                }
                #pragma unroll
                for (int ci = 0; ci < 4; ci++)
                    #pragma unroll
                    for (int p = 0; p < 2; p++) {
                        float lo, hi; unpack2(acc[ci][p], lo, hi);
                        int rr = rbase + 2 * p;
                        xs_sh[rr * XS_COLS + jl + ci]       = lo + bbv[ci] + hvv[2 * p][ci];
                        xs_sh[(rr + 1) * XS_COLS + jl + ci] = hi + bbv[ci] + hvv[2 * p + 1][ci];
                    }
            }
        }
        group_barrier(g, &bar_target);   // r*s, z visible group-wide

        //==================== B: m = (r*s)@U_s, then s_t.  K=512 ====================
        // stage rsT (transposed pairs)
        for (int i = tid; i < RG * HDIM / 2; i += NTH) {
            int q = i >> 9, k = i & 511;
            float lo = g_rs[(row0 + 2 * q) * HDIM + k];
            float hi = g_rs[(row0 + 2 * q + 1) * HDIM + k];
            *(u64*)(rsT + k * AST + 2 * q) = pack2(lo, hi);
        }
        __syncthreads();
        {
            int kq = wrp;
            int cg = lane & 3, rg = lane >> 2;
            int jl = cg * 4;
            int jcol = 1024 + kcs + jl;
            int rbase = rg * 4;

            float4 zv4[4];
            if (kq == 0) {
                const float* zp = g_z + (size_t)(row0 + rbase) * HDIM + kcs + jl;
                #pragma unroll
                for (int r = 0; r < 4; r++) zv4[r] = *(const float4*)(zp + (size_t)r * HDIM);
            }

            u64 acc[4][2];
            #pragma unroll
            for (int ci = 0; ci < 4; ci++) { acc[ci][0] = 0ull; acc[ci][1] = 0ull; }

            int k0 = kq * 32;
            const float* up = U + (size_t)k0 * NCOL + jcol;
            #pragma unroll 8
            for (int k = k0; k < k0 + 32; k++, up += NCOL) {
                float4 wv = *(const float4*)up;
                const u64* ap = (const u64*)(rsT + k * AST + rbase);
                u64 a0 = ap[0], a1 = ap[1];
                u64 w0 = dup2(wv.x), w1 = dup2(wv.y), w2 = dup2(wv.z), w3 = dup2(wv.w);
                fma2(acc[0][0], a0, w0); fma2(acc[0][1], a1, w0);
                fma2(acc[1][0], a0, w1); fma2(acc[1][1], a1, w1);
                fma2(acc[2][0], a0, w2); fma2(acc[2][1], a1, w2);
                fma2(acc[3][0], a0, w3); fma2(acc[3][1], a1, w3);
            }
            if (kq > 0) {
                int base = (kq - 1) * 256;
                #pragma unroll
                for (int ci = 0; ci < 4; ci++)
                    #pragma unroll
                    for (int p = 0; p < 2; p++) {
                        int sidx = (jl + ci) * 16 + ((rg * 2 + p + cg * 4) & 15);
                        red64[base + sidx] = acc[ci][p];
                    }
            }
            __syncthreads();
            if (kq == 0) {
                #pragma unroll
                for (int l = 0; l < 15; l++)
                    #pragma unroll
                    for (int ci = 0; ci < 4; ci++)
                        #pragma unroll
                        for (int p = 0; p < 2; p++) {
                            int sidx = (jl + ci) * 16 + ((rg * 2 + p + cg * 4) & 15);
                            acc[ci][p] = add2(acc[ci][p], red64[l * 256 + sidx]);
                        }
                float zvv[4][4];
                #pragma unroll
                for (int r = 0; r < 4; r++) {
                    zvv[r][0] = zv4[r].x; zvv[r][1] = zv4[r].y;
                    zvv[r][2] = zv4[r].z; zvv[r][3] = zv4[r].w;
                }
                #pragma unroll
                for (int ci = 0; ci < 4; ci++) {
                    int kglob = kcs + jl + ci;
                    #pragma unroll
                    for (int p = 0; p < 2; p++) {
                        float lo, hi; unpack2(acc[ci][p], lo, hi);
                        #pragma unroll
                        for (int pr = 0; pr < 2; pr++) {
                            int rr = rbase + 2 * p + pr;
                            float m  = pr ? hi : lo;
                            float s1 = tanhf(xs_sh[rr * XS_COLS + jl + ci] + m);
                            float zv = zvv[2 * p + pr][ci];
                            float sold = actT[(256 + kglob) * AST + rr];
                            g_s[(row0 + rr) * HDIM + kglob] = (1.0f - zv) * sold + zv * s1;
                        }
                    }
                }
            }
        }
        group_barrier(g, &bar_target);   // s_t visible group-wide

        //==================== C: x_t = tanh(s_t @ Wxo + bx).  K=512 ====================
        // stage s_t into actT (also serves next step's A)
        for (int i = tid; i < RG * HDIM / 2; i += NTH) {
            int q = i >> 9, k = i & 511;
            float lo = g_s[(row0 + 2 * q) * HDIM + k];
            float hi = g_s[(row0 + 2 * q + 1) * HDIM + k];
            *(u64*)(actT + (256 + k) * AST + 2 * q) = pack2(lo, hi);
        }
        __syncthreads();
        {
            int kq = wrp;
            int cg = lane & 1, rg = lane >> 1;   // 2 col-groups of 4, 16 row-groups of 2
            int jl = cg * 4;
            int oc0 = o0 + jl;
            int rbase = rg * 2;

            u64 acc[4];
            #pragma unroll
            for (int ci = 0; ci < 4; ci++) acc[ci] = 0ull;

            int k0 = kq * 32;
            const float* wp = Wx + (size_t)k0 * (3 * ODIM) + oc0;
            #pragma unroll 8
            for (int k = k0; k < k0 + 32; k++, wp += 3 * ODIM) {
                float4 wv = *(const float4*)wp;
                u64 a0 = *(const u64*)(actT + (256 + k) * AST + rbase);
                fma2(acc[0], a0, dup2(wv.x));
                fma2(acc[1], a0, dup2(wv.y));
                fma2(acc[2], a0, dup2(wv.z));
                fma2(acc[3], a0, dup2(wv.w));
            }
            if (kq > 0) {
                int base = (kq - 1) * 128;
                #pragma unroll
                for (int ci = 0; ci < 4; ci++) {
                    int sidx = (jl + ci) * 16 + ((rg + cg * 8) & 15);
                    red64[base + sidx] = acc[ci];
                }
            }
            __syncthreads();
            if (kq == 0) {
                #pragma unroll
                for (int l = 0; l < 15; l++)
                    #pragma unroll
                    for (int ci = 0; ci < 4; ci++) {
                        int sidx = (jl + ci) * 16 + ((rg + cg * 8) & 15);
                        acc[ci] = add2(acc[ci], red64[l * 128 + sidx]);
                    }
                float4 bx4 = *(const float4*)(bx + oc0);
                float bxv[4] = { bx4.x, bx4.y, bx4.z, bx4.w };
                #pragma unroll
                for (int ci = 0; ci < 4; ci++) {
                    int oc = oc0 + ci;
                    float lo, hi; unpack2(acc[ci], lo, hi);
                    float x0v = tanhf(lo + bxv[ci]);
                    float x1v = tanhf(hi + bxv[ci]);
                    g_x[(row0 + rbase) * ODIM + oc]     = x0v;
                    g_x[(row0 + rbase + 1) * ODIM + oc] = x1v;
                    out[((size_t)(row0 + rbase) * TT + t) * ODIM + oc]     = x0v;
                    out[((size_t)(row0 + rbase + 1) * TT + t) * ODIM + oc] = x1v;
                }
            }
        }
        group_barrier(g, &bar_target);   // x_t visible group-wide

        // restage x for next step (paired)
        for (int i = tid; i < RG * ODIM / 2; i += NTH) {
            int q = i >> 8, k = i & 255;
            float lo = g_x[(row0 + 2 * q) * ODIM + k];
            float hi = g_x[(row0 + 2 * q + 1) * ODIM + k];
            *(u64*)(actT + k * AST + 2 * q) = pack2(lo, hi);
        }
        __syncthreads();
    }
}

// ---------------- launch ----------------
extern "C" void kernel_launch(void* const* d_in, const int* in_sizes, int n_in,
                              void* d_out, int out_size) {
    const float* H  = (const float*)d_in[0];
    const float* W  = (const float*)d_in[1];
    const float* Bb = (const float*)d_in[2];
    const float* U  = (const float*)d_in[3];
    const float* Wx = (const float*)d_in[4];
    const float* bx = (const float*)d_in[5];
    const float* Vr = (const float*)d_in[6];
    const float* Vz = (const float*)d_in[7];
    const float* Vs = (const float*)d_in[8];
    float* out = (float*)d_out;

    const size_t smem_bytes = (size_t)SM_TOTAL * sizeof(float);  // 206,848 B
    cudaFuncSetAttribute(recur_kernel, cudaFuncAttributeMaxDynamicSharedMemorySize,
                         (int)smem_bytes);

    hv_gemm<<<dim3(12, 512), 256>>>(H, Vr, Vz, Vs);
    recur_kernel<<<NCTA, NTH, smem_bytes>>>(H, W, Bb, U, Wx, bx, out);
}

// round 8
// speedup vs baseline: 2.3316x; 1.1199x over previous
#include <cuda_runtime.h>
#include <math.h>
#include <stdint.h>

// Problem dims
#define BATCH 128
#define TT    512
#define DIM   512
#define HDIM  512
#define ODIM  256
#define NCOL  1536   // 3*HDIM

// Recurrence partition: 4 row-groups x 32 rows; 32 CTAs per group (column slices)
#define NG  4
#define RG  32
#define NC  32
#define NCTA (NG*NC)
#define NTH 512      // 16 warps

#define RZ_COLS 32   // pre-activation columns in [0,1024) per CTA
#define XS_COLS 16   // hdim slice of [1024,1536) per CTA
#define XO_COLS 8    // output columns of Wxo per CTA

// Shared memory layout (floats). AST=34 (even -> 8B-aligned u64 rows).
#define AST      34
#define SM_ACT   0
#define SM_RS    (768*AST)                 // 26112
#define SM_RED   (SM_RS + 512*AST)         // 43520 (even -> u64-aligned)
#define SM_TOTAL (SM_RED + 8192)           // 51712 floats = 206848 bytes

typedef unsigned long long u64;

__device__ __forceinline__ u64 pack2(float lo, float hi) {
    u64 r; asm("mov.b64 %0,{%1,%2};" : "=l"(r) : "f"(lo), "f"(hi)); return r;
}
__device__ __forceinline__ void unpack2(u64 v, float& lo, float& hi) {
    asm("mov.b64 {%0,%1},%2;" : "=f"(lo), "=f"(hi) : "l"(v));
}
__device__ __forceinline__ void fma2(u64& d, u64 a, u64 b) {
    asm("fma.rn.f32x2 %0,%1,%2,%0;" : "+l"(d) : "l"(a), "l"(b));
}
__device__ __forceinline__ u64 add2(u64 a, u64 b) {
    u64 r; asm("add.rn.f32x2 %0,%1,%2;" : "=l"(r) : "l"(a), "l"(b)); return r;
}
__device__ __forceinline__ u64 dup2(float w) { return pack2(w, w); }

// ---------------- device scratch ----------------
__device__ float g_hV[(size_t)TT * BATCH * NCOL];  // precomputed hV[t][b][j]
// group-local, column-major exchange buffers: [group][col][row]
__device__ float g_rs[NG][HDIM][RG];
__device__ float g_z [NG][HDIM][RG];
__device__ float g_s [NG][HDIM][RG];
__device__ float g_x [NG][ODIM][RG];
__device__ unsigned g_bar[NG];

__device__ __forceinline__ float sigf(float x) { return 1.0f / (1.0f + expf(-x)); }

// ---------------- hV GEMM (f32x2) ----------------
#define GT_N 128
#define GT_K 8
__global__ void __launch_bounds__(256, 2)
hv_gemm(const float* __restrict__ H,
        const float* __restrict__ Vr,
        const float* __restrict__ Vz,
        const float* __restrict__ Vs) {
    if (blockIdx.x == 0 && blockIdx.y == 0 && threadIdx.x < NG)
        g_bar[threadIdx.x] = 0u;

    int t  = blockIdx.y;
    int jt = blockIdx.x;
    const float* V = (jt < 4) ? Vr : ((jt < 8) ? Vz : Vs);
    int col0 = (jt & 3) * GT_N;
    const float* A = H + (size_t)(TT - 1 - t) * DIM;

    __shared__ float Ash[GT_K][BATCH + 4];
    __shared__ float Bsh[GT_K][GT_N];

    int tx = threadIdx.x & 15, ty = threadIdx.x >> 4;
    u64 acc[4][8];
    #pragma unroll
    for (int i = 0; i < 4; i++)
        #pragma unroll
        for (int j = 0; j < 8; j++) acc[i][j] = 0ull;

    for (int k0 = 0; k0 < DIM; k0 += GT_K) {
        for (int i = threadIdx.x; i < BATCH * GT_K; i += 256) {
            int bb = i >> 3, dd = i & 7;
            Ash[dd][bb] = A[(size_t)bb * (TT * DIM) + k0 + dd];
        }
        for (int i = threadIdx.x; i < GT_K * GT_N; i += 256) {
            int dd = i >> 7, jj = i & 127;
            Bsh[dd][jj] = V[(size_t)(k0 + dd) * HDIM + col0 + jj];
        }
        __syncthreads();
        #pragma unroll
        for (int kk = 0; kk < GT_K; kk++) {
            const u64* ap0 = (const u64*)&Ash[kk][ty * 4];
            const u64* ap1 = (const u64*)&Ash[kk][64 + ty * 4];
            u64 av[4] = { ap0[0], ap0[1], ap1[0], ap1[1] };
            u64 bv[8];
            #pragma unroll
            for (int j = 0; j < 8; j++) {
                float b = (j < 4) ? Bsh[kk][tx * 4 + j] : Bsh[kk][64 + tx * 4 + (j - 4)];
                bv[j] = dup2(b);
            }
            #pragma unroll
            for (int i = 0; i < 4; i++)
                #pragma unroll
                for (int j = 0; j < 8; j++)
                    fma2(acc[i][j], av[i], bv[j]);
        }
        __syncthreads();
    }
    float* outp = g_hV + (size_t)t * BATCH * NCOL + jt * GT_N;
    int rowb[4] = { ty * 4, ty * 4 + 2, 64 + ty * 4, 64 + ty * 4 + 2 };
    #pragma unroll
    for (int i = 0; i < 4; i++)
        #pragma unroll
        for (int j = 0; j < 8; j++) {
            float lo, hi; unpack2(acc[i][j], lo, hi);
            int jc = (j < 4) ? (tx * 4 + j) : (64 + tx * 4 + (j - 4));
            outp[(size_t)rowb[i] * NCOL + jc]       = lo;
            outp[(size_t)(rowb[i] + 1) * NCOL + jc] = hi;
        }
}

// ---------------- group barrier (acquire/release) ----------------
__device__ __forceinline__ void group_barrier(int g, unsigned* target) {
    __syncthreads();
    if (threadIdx.x == 0) {
        unsigned tg = (*target += NC);
        asm volatile("red.release.gpu.global.add.u32 [%0], 1;"
                     :: "l"(&g_bar[g]) : "memory");
        unsigned v;
        do {
            asm volatile("ld.acquire.gpu.global.u32 %0, [%1];"
                         : "=r"(v) : "l"(&g_bar[g]) : "memory");
        } while (v < tg);
    }
    __syncthreads();
}

// ---------------- persistent recurrence kernel: 128 CTAs x 512 threads ----------------
__global__ void __launch_bounds__(NTH, 1)
recur_kernel(const float* __restrict__ H,   // for x0
             const float* __restrict__ W,   // [256][1536]
             const float* __restrict__ Bb,  // [1536]
             const float* __restrict__ U,   // [512][1536]
             const float* __restrict__ Wx,  // [512][768], Wxo = cols [0,256)
             const float* __restrict__ bx,  // [256]
             float* __restrict__ out)       // [128][512][256]
{
    extern __shared__ float sm[];
    float* actT  = sm + SM_ACT;   // [768][34] transposed: rows 0..255 x, 256..767 s
    float* rsT   = sm + SM_RS;    // [512][34] transposed r*s
    u64*   red64 = (u64*)(sm + SM_RED);  // k-split partials (4096 u64)

    const int cta = blockIdx.x;
    const int g   = cta >> 5;
    const int c   = cta & 31;
    const int tid = threadIdx.x;
    const int row0 = g * RG;

    const int jrz = c * RZ_COLS;
    const int kcs = c * XS_COLS;
    const int o0  = c * XO_COLS;

    const int lane = tid & 31;
    const int wrp  = tid >> 5;

    // consumer mapping (thread -> (col, row-pair))
    const int ccol = tid >> 4;     // 0..31
    const int crp  = tid & 15;     // 0..15
    const int cr0  = 2 * crp;

    unsigned bar_target = 0;

    // hoisted biases
    const float biasA1 = __ldg(Bb + jrz + ccol);
    const float biasA2 = (tid < 256) ? __ldg(Bb + 1024 + kcs + ccol) : 0.0f;
    const float biasC  = (tid < 128) ? __ldg(bx + o0 + ccol) : 0.0f;

    // Initial staging: x0 directly from H, s = 0
    for (int i = tid; i < RG * ODIM; i += NTH) {
        int r = i >> 8, k = i & 255;
        const float* h = H + ((size_t)(row0 + r) * TT + (TT - 1)) * DIM;
        actT[k * AST + r] = h[k] + h[k + ODIM];
    }
    for (int i = tid; i < RG * HDIM / 2; i += NTH) {
        int q = i >> 9, k = i & 511;
        *(u64*)(actT + (256 + k) * AST + 2 * q) = 0ull;
    }
    __syncthreads();

    for (int t = 0; t < TT; t++) {
        const float* hvt = g_hV + (size_t)t * BATCH * NCOL;

        // --------- per-thread epilogue prefetches (overlap with A1 GEMV) ---------
        float hvA_lo, hvA_hi, hv2_lo = 0.f, hv2_hi = 0.f;
        {
            const float* p = hvt + (size_t)(row0 + cr0) * NCOL + jrz + ccol;
            hvA_lo = __ldg(p);
            hvA_hi = __ldg(p + NCOL);
            if (tid < 256) {
                const float* p2 = hvt + (size_t)(row0 + cr0) * NCOL + 1024 + kcs + ccol;
                hv2_lo = __ldg(p2);
                hv2_hi = __ldg(p2 + NCOL);
            }
        }

        //==================== A1 GEMV: j in [0,1024), K=768 ====================
        // warp = ch(2 col-halves of 16) x kq(8-way k-split of 96)
        // lane = cg(4 col-groups of 4) x rg(8 row-groups of 4)
        {
            int ch = wrp & 1, kq = wrp >> 1;
            int cg = lane & 3, rg = lane >> 2;
            int jl = ch * 16 + cg * 4;
            int j0 = jrz + jl;
            int rbase = rg * 4;

            u64 acc[4][2];
            #pragma unroll
            for (int ci = 0; ci < 4; ci++) { acc[ci][0] = 0ull; acc[ci][1] = 0ull; }

            int k0 = kq * 96, k1 = k0 + 96;
            int ke = (k1 < 256) ? k1 : 256;          // x part (W rows)
            const float* wp = W + (size_t)k0 * NCOL + j0;
            #pragma unroll 8
            for (int k = k0; k < ke; k++, wp += NCOL) {
                float4 wv = *(const float4*)wp;
                const u64* ap = (const u64*)(actT + k * AST + rbase);
                u64 a0 = ap[0], a1 = ap[1];
                u64 w0 = dup2(wv.x), w1 = dup2(wv.y), w2 = dup2(wv.z), w3 = dup2(wv.w);
                fma2(acc[0][0], a0, w0); fma2(acc[0][1], a1, w0);
                fma2(acc[1][0], a0, w1); fma2(acc[1][1], a1, w1);
                fma2(acc[2][0], a0, w2); fma2(acc[2][1], a1, w2);
                fma2(acc[3][0], a0, w3); fma2(acc[3][1], a1, w3);
            }
            int kb = (k0 > 256) ? k0 : 256;          // s part (U rows)
            const float* up = U + (size_t)(kb - 256) * NCOL + j0;
            #pragma unroll 8
            for (int k = kb; k < k1; k++, up += NCOL) {
                float4 wv = *(const float4*)up;
                const u64* ap = (const u64*)(actT + k * AST + rbase);
                u64 a0 = ap[0], a1 = ap[1];
                u64 w0 = dup2(wv.x), w1 = dup2(wv.y), w2 = dup2(wv.z), w3 = dup2(wv.w);
                fma2(acc[0][0], a0, w0); fma2(acc[0][1], a1, w0);
                fma2(acc[1][0], a0, w1); fma2(acc[1][1], a1, w1);
                fma2(acc[2][0], a0, w2); fma2(acc[2][1], a1, w2);
                fma2(acc[3][0], a0, w3); fma2(acc[3][1], a1, w3);
            }
            int base = kq * 512;
            #pragma unroll
            for (int ci = 0; ci < 4; ci++)
                #pragma unroll
                for (int p = 0; p < 2; p++) {
                    int sidx = (jl + ci) * 16 + ((rg * 2 + p + cg * 4) & 15);
                    red64[base + sidx] = acc[ci][p];
                }
        }
        __syncthreads();
        // --------- A1 epilogue: distributed over all 512 threads ---------
        {
            int j = jrz + ccol;
            int sidx = ccol * 16 + ((crp + ((ccol >> 2) & 3) * 4) & 15);
            u64 acc = red64[sidx];
            #pragma unroll
            for (int l = 1; l < 8; l++) acc = add2(acc, red64[l * 512 + sidx]);
            float a0, a1; unpack2(acc, a0, a1);
            a0 += biasA1 + hvA_lo;
            a1 += biasA1 + hvA_hi;
            if (jrz < HDIM) {   // whole CTA is r-gate
                float s0, s1; unpack2(*(const u64*)(actT + (256 + j) * AST + cr0), s0, s1);
                *(u64*)&g_rs[g][j][cr0] = pack2(sigf(a0) * s0, sigf(a1) * s1);
            } else {            // whole CTA is z-gate
                *(u64*)&g_z[g][j - HDIM][cr0] = pack2(sigf(a0), sigf(a1));
            }
        }
        __syncthreads();   // red free for A2

        //==================== A2 GEMV: j in [1024,1536), K=256 ====================
        // warp = kq(16-way split of 16); lane = cg(4 col-groups of 4) x rg(8)
        {
            int kq = wrp;
            int cg = lane & 3, rg = lane >> 2;
            int jl = cg * 4;
            int j0 = 1024 + kcs + jl;
            int rbase = rg * 4;

            u64 acc[4][2];
            #pragma unroll
            for (int ci = 0; ci < 4; ci++) { acc[ci][0] = 0ull; acc[ci][1] = 0ull; }

            int k0 = kq * 16;
            const float* wp = W + (size_t)k0 * NCOL + j0;
            #pragma unroll 8
            for (int k = k0; k < k0 + 16; k++, wp += NCOL) {
                float4 wv = *(const float4*)wp;
                const u64* ap = (const u64*)(actT + k * AST + rbase);
                u64 a0 = ap[0], a1 = ap[1];
                u64 w0 = dup2(wv.x), w1 = dup2(wv.y), w2 = dup2(wv.z), w3 = dup2(wv.w);
                fma2(acc[0][0], a0, w0); fma2(acc[0][1], a1, w0);
                fma2(acc[1][0], a0, w1); fma2(acc[1][1], a1, w1);
                fma2(acc[2][0], a0, w2); fma2(acc[2][1], a1, w2);
                fma2(acc[3][0], a0, w3); fma2(acc[3][1], a1, w3);
            }
            int base = kq * 256;
            #pragma unroll
            for (int ci = 0; ci < 4; ci++)
                #pragma unroll
                for (int p = 0; p < 2; p++) {
                    int sidx = (jl + ci) * 16 + ((rg * 2 + p + cg * 4) & 15);
                    red64[base + sidx] = acc[ci][p];
                }
        }
        __syncthreads();
        // --------- A2 epilogue -> xs stays in registers (same thread uses it in B) ---------
        float xs_lo = 0.f, xs_hi = 0.f;
        if (tid < 256) {
            int sidx = ccol * 16 + ((crp + ((ccol >> 2) & 3) * 4) & 15);
            u64 acc = red64[sidx];
            #pragma unroll
            for (int l = 1; l < 16; l++) acc = add2(acc, red64[l * 256 + sidx]);
            float a0, a1; unpack2(acc, a0, a1);
            xs_lo = a0 + biasA2 + hv2_lo;
            xs_hi = a1 + biasA2 + hv2_hi;
        }
        group_barrier(g, &bar_target);   // r*s, z visible group-wide

        //==================== B: m = (r*s)@U_s, then s_t.  K=512 ====================
        u64 zv = 0ull;
        if (tid < 256) zv = *(const u64*)&g_z[g][kcs + ccol][cr0];
        // stage rsT (coalesced u64 from column-major g_rs)
        for (int i = tid; i < RG * HDIM / 2; i += NTH) {
            int k = i >> 4, q = i & 15;
            *(u64*)(rsT + k * AST + 2 * q) = *(const u64*)&g_rs[g][k][2 * q];
        }
        __syncthreads();
        {
            int kq = wrp;
            int cg = lane & 3, rg = lane >> 2;
            int jl = cg * 4;
            int jcol = 1024 + kcs + jl;
            int rbase = rg * 4;

            u64 acc[4][2];
            #pragma unroll
            for (int ci = 0; ci < 4; ci++) { acc[ci][0] = 0ull; acc[ci][1] = 0ull; }

            int k0 = kq * 32;
            const float* up = U + (size_t)k0 * NCOL + jcol;
            #pragma unroll 8
            for (int k = k0; k < k0 + 32; k++, up += NCOL) {
                float4 wv = *(const float4*)up;
                const u64* ap = (const u64*)(rsT + k * AST + rbase);
                u64 a0 = ap[0], a1 = ap[1];
                u64 w0 = dup2(wv.x), w1 = dup2(wv.y), w2 = dup2(wv.z), w3 = dup2(wv.w);
                fma2(acc[0][0], a0, w0); fma2(acc[0][1], a1, w0);
                fma2(acc[1][0], a0, w1); fma2(acc[1][1], a1, w1);
                fma2(acc[2][0], a0, w2); fma2(acc[2][1], a1, w2);
                fma2(acc[3][0], a0, w3); fma2(acc[3][1], a1, w3);
            }
            int base = kq * 256;
            #pragma unroll
            for (int ci = 0; ci < 4; ci++)
                #pragma unroll
                for (int p = 0; p < 2; p++) {
                    int sidx = (jl + ci) * 16 + ((rg * 2 + p + cg * 4) & 15);
                    red64[base + sidx] = acc[ci][p];
                }
        }
        __syncthreads();
        // --------- B epilogue: s_t (distributed, 256 threads) ---------
        if (tid < 256) {
            int kglob = kcs + ccol;
            int sidx = ccol * 16 + ((crp + ((ccol >> 2) & 3) * 4) & 15);
            u64 acc = red64[sidx];
            #pragma unroll
            for (int l = 1; l < 16; l++) acc = add2(acc, red64[l * 256 + sidx]);
            float m0, m1; unpack2(acc, m0, m1);
            float z0, z1; unpack2(zv, z0, z1);
            float s1a = tanhf(xs_lo + m0);
            float s1b = tanhf(xs_hi + m1);
            float so0, so1; unpack2(*(const u64*)(actT + (256 + kglob) * AST + cr0), so0, so1);
            *(u64*)&g_s[g][kglob][cr0] =
                pack2((1.0f - z0) * so0 + z0 * s1a, (1.0f - z1) * so1 + z1 * s1b);
        }
        group_barrier(g, &bar_target);   // s_t visible group-wide

        //==================== C: x_t = tanh(s_t @ Wxo + bx).  K=512 ====================
        // stage s_t into actT (also serves next step's A)
        for (int i = tid; i < RG * HDIM / 2; i += NTH) {
            int k = i >> 4, q = i & 15;
            *(u64*)(actT + (256 + k) * AST + 2 * q) = *(const u64*)&g_s[g][k][2 * q];
        }
        __syncthreads();
        {
            int kq = wrp;
            int cg = lane & 1, rg = lane >> 1;   // 2 col-groups of 4, 16 row-pairs
            int jl = cg * 4;
            int oc0 = o0 + jl;
            int rbase = rg * 2;

            u64 acc[4];
            #pragma unroll
            for (int ci = 0; ci < 4; ci++) acc[ci] = 0ull;

            int k0 = kq * 32;
            const float* wp = Wx + (size_t)k0 * (3 * ODIM) + oc0;
            #pragma unroll 8
            for (int k = k0; k < k0 + 32; k++, wp += 3 * ODIM) {
                float4 wv = *(const float4*)wp;
                u64 a0 = *(const u64*)(actT + (256 + k) * AST + rbase);
                fma2(acc[0], a0, dup2(wv.x));
                fma2(acc[1], a0, dup2(wv.y));
                fma2(acc[2], a0, dup2(wv.z));
                fma2(acc[3], a0, dup2(wv.w));
            }
            int base = kq * 128;
            #pragma unroll
            for (int ci = 0; ci < 4; ci++) {
                int sidx = (jl + ci) * 16 + ((rg + cg * 8) & 15);
                red64[base + sidx] = acc[ci];
            }
        }
        __syncthreads();
        // --------- C epilogue: x_t (distributed, 128 threads) ---------
        if (tid < 128) {
            int oc = o0 + ccol;
            int sidx = ccol * 16 + ((crp + ((ccol >> 2) & 1) * 8) & 15);
            u64 acc = red64[sidx];
            #pragma unroll
            for (int l = 1; l < 16; l++) acc = add2(acc, red64[l * 128 + sidx]);
            float a0, a1; unpack2(acc, a0, a1);
            float x0v = tanhf(a0 + biasC);
            float x1v = tanhf(a1 + biasC);
            *(u64*)&g_x[g][oc][cr0] = pack2(x0v, x1v);
            out[((size_t)(row0 + cr0) * TT + t) * ODIM + oc]     = x0v;
            out[((size_t)(row0 + cr0 + 1) * TT + t) * ODIM + oc] = x1v;
        }
        group_barrier(g, &bar_target);   // x_t visible group-wide

        // restage x for next step (coalesced u64)
        for (int i = tid; i < RG * ODIM / 2; i += NTH) {
            int k = i >> 4, q = i & 15;
            *(u64*)(actT + k * AST + 2 * q) = *(const u64*)&g_x[g][k][2 * q];
        }
        __syncthreads();
    }
}

// ---------------- launch ----------------
extern "C" void kernel_launch(void* const* d_in, const int* in_sizes, int n_in,
                              void* d_out, int out_size) {
    const float* H  = (const float*)d_in[0];
    const float* W  = (const float*)d_in[1];
    const float* Bb = (const float*)d_in[2];
    const float* U  = (const float*)d_in[3];
    const float* Wx = (const float*)d_in[4];
    const float* bx = (const float*)d_in[5];
    const float* Vr = (const float*)d_in[6];
    const float* Vz = (const float*)d_in[7];
    const float* Vs = (const float*)d_in[8];
    float* out = (float*)d_out;

    const size_t smem_bytes = (size_t)SM_TOTAL * sizeof(float);  // 206,848 B
    cudaFuncSetAttribute(recur_kernel, cudaFuncAttributeMaxDynamicSharedMemorySize,
                         (int)smem_bytes);

    hv_gemm<<<dim3(12, 512), 256>>>(H, Vr, Vz, Vs);
    recur_kernel<<<NCTA, NTH, smem_bytes>>>(H, W, Bb, U, Wx, bx, out);
}